// round 14
// baseline (speedup 1.0000x reference)
#include <cuda_runtime.h>
#include <cuda_fp16.h>
#include <stdint.h>

#define N_NODES     50000
#define N_EDGES     500000
#define D_FEAT      128
#define OUT_CLASSES 64
#define PDIM        128   // [0:64) = Pu (+bias folded), [64:128) = Pv

#define NB          592   // 148 SMs x 4 CTAs: entire grid co-resident
#define GM          64
#define GEMM_TILES  ((N_NODES + GM - 1) / GM)     // 782
#define CHUNKS      ((N_EDGES + 63) / 64)         // 7813 (64 edges each)

#define ST   68   // uint32 per row (64 f16x2 pairs + 4 pad); 68 mod 32 = 4
#define GEMM_SMEM ((64 + 128) * ST * 4)   // 52,224 B -> 4 CTAs/SM = 208.9KB

// Per-node projections in fp16; 12.8 MB, L2-resident.
__device__ __align__(16) __half g_P[N_NODES * PDIM];
// Grid barrier: monotonic, replay-safe (each launch adds exactly NB).
__device__ unsigned g_bar = 0;

// ---------------------------------------------------------------------------
// Single-pass fp16 mma (legacy mma.sync — tcgen05 unavailable at compute_103).
// Measured error: 3.595e-4 (fp16-A/B/P in quadrature) << 1e-3.
// ---------------------------------------------------------------------------
__device__ __forceinline__ void mma_f16(float d[4], const uint32_t a[4], const uint32_t b[2]) {
    asm volatile(
        "mma.sync.aligned.m16n8k16.row.col.f32.f16.f16.f32 "
        "{%0,%1,%2,%3}, {%4,%5,%6,%7}, {%8,%9}, {%0,%1,%2,%3};\n"
        : "+f"(d[0]), "+f"(d[1]), "+f"(d[2]), "+f"(d[3])
        : "r"(a[0]), "r"(a[1]), "r"(a[2]), "r"(a[3]), "r"(b[0]), "r"(b[1]));
}

// ---------------------------------------------------------------------------
// ONE persistent kernel: phase 1 = node GEMM (grid-stride over 782 tiles),
// software grid barrier (all 592 CTAs co-resident by construction),
// phase 2 = edge scatter (grid-stride over 7813 64-edge chunks).
// Removes one ~4us kernel-launch floor.
// ---------------------------------------------------------------------------
__global__ __launch_bounds__(256, 4)
void fused_kernel(const float* __restrict__ h,
                  const float* __restrict__ W,
                  const float* __restrict__ b,
                  const void*  __restrict__ srcp,
                  const void*  __restrict__ dstp,
                  float* __restrict__ out) {
    extern __shared__ uint32_t sh[];
    uint32_t* Ah = sh;               // [64][ST]  f16x2 pairs, k-major
    uint32_t* Bs = sh + 64 * ST;     // [128][ST] f16x2 pairs, k-major
    __shared__ int s_is64;

    const int tid  = threadIdx.x;
    const int wid  = tid >> 5;
    const int lane = tid & 31;

    // ============================ Phase 1: GEMM ============================
    {
        const int warp_m = wid & 1;
        const int warp_n = wid >> 1;
        const int m_base = warp_m * 32;
        const int n_base = warp_n * 32;
        const int lr = lane >> 2;
        const int lc = lane & 3;

        for (int tile = blockIdx.x; tile < GEMM_TILES; tile += NB) {
            if (tile != (int)blockIdx.x) __syncthreads();  // smem reuse
            const int n0 = tile * GM;

            // Stage A (h tile, 64 x 128 f32 -> f16x2), coalesced float4
            #pragma unroll
            for (int it = 0; it < 8; ++it) {
                int idx = tid + it * 256;
                int r  = idx >> 5;
                int c4 = idx & 31;
                int node = n0 + r;
                float4 v = make_float4(0.f, 0.f, 0.f, 0.f);
                if (node < N_NODES)
                    v = __ldg((const float4*)&h[(size_t)node * D_FEAT + c4 * 4]);
                __half2 h0 = __floats2half2_rn(v.x, v.y);
                __half2 h1 = __floats2half2_rn(v.z, v.w);
                *(uint2*)&Ah[r * ST + c4 * 2] =
                    make_uint2(*(uint32_t*)&h0, *(uint32_t*)&h1);
            }
            // Stage B (Wn, 128 x 128 f32 -> f16x2), coalesced float4 per row
            #pragma unroll
            for (int it = 0; it < 16; ++it) {
                int idx = tid + it * 256;
                int j  = idx >> 5;
                int c4 = idx & 31;
                const float* ws = (j < OUT_CLASSES)
                    ? &W[(size_t)j * 256 + c4 * 4]
                    : &W[(size_t)(j - OUT_CLASSES) * 256 + 128 + c4 * 4];
                float4 v = __ldg((const float4*)ws);
                __half2 h0 = __floats2half2_rn(v.x, v.y);
                __half2 h1 = __floats2half2_rn(v.z, v.w);
                *(uint2*)&Bs[j * ST + c4 * 2] =
                    make_uint2(*(uint32_t*)&h0, *(uint32_t*)&h1);
            }
            __syncthreads();

            float acc[2][4][4];
            #pragma unroll
            for (int a = 0; a < 2; ++a)
                #pragma unroll
                for (int bn = 0; bn < 4; ++bn)
                    #pragma unroll
                    for (int c = 0; c < 4; ++c) acc[a][bn][c] = 0.0f;

            #pragma unroll 2
            for (int kc = 0; kc < 8; ++kc) {
                const int p0 = kc * 8 + lc;

                uint32_t bb[4][2];
                #pragma unroll
                for (int bn = 0; bn < 4; ++bn) {
                    int nb = (n_base + bn * 8 + lr) * ST + p0;
                    bb[bn][0] = Bs[nb];
                    bb[bn][1] = Bs[nb + 4];
                }
                uint32_t ah[2][4];
                #pragma unroll
                for (int am = 0; am < 2; ++am) {
                    int base = (m_base + am * 16 + lr) * ST + p0;
                    ah[am][0] = Ah[base];
                    ah[am][1] = Ah[base + 8 * ST];
                    ah[am][2] = Ah[base + 4];
                    ah[am][3] = Ah[base + 8 * ST + 4];
                }
                #pragma unroll
                for (int am = 0; am < 2; ++am)
                    #pragma unroll
                    for (int bn = 0; bn < 4; ++bn)
                        mma_f16(acc[am][bn], ah[am], bb[bn]);
            }

            // Epilogue: fp16 P, bias folded into Pu columns.
            #pragma unroll
            for (int am = 0; am < 2; ++am) {
                int row = m_base + am * 16 + lr;
                #pragma unroll
                for (int bn = 0; bn < 4; ++bn) {
                    int j = n_base + bn * 8 + 2 * lc;
                    float bx = 0.f, by = 0.f;
                    if (warp_n < 2) {
                        float2 bv = __ldg((const float2*)&b[j]);
                        bx = bv.x; by = bv.y;
                    }
                    int node = n0 + row;
                    if (node < N_NODES) {
                        __half2 v0 = __floats2half2_rn(acc[am][bn][0] + bx,
                                                       acc[am][bn][1] + by);
                        *(__half2*)&g_P[(size_t)node * PDIM + j] = v0;
                    }
                    int node2 = n0 + row + 8;
                    if (node2 < N_NODES) {
                        __half2 v1 = __floats2half2_rn(acc[am][bn][2] + bx,
                                                       acc[am][bn][3] + by);
                        *(__half2*)&g_P[(size_t)node2 * PDIM + j] = v1;
                    }
                }
            }
        }
    }

    // ========================= Grid barrier ================================
    // Monotonic counter: each launch adds exactly NB, so target is the next
    // multiple of NB above my ticket. Replay-safe, no reset, deterministic.
    __threadfence();                        // publish g_P
    if (tid == 0) {
        unsigned t = atomicAdd(&g_bar, 1u);
        unsigned target = (t / NB + 1u) * NB;
        while (*(volatile unsigned*)&g_bar < target) { }
        __threadfence();                    // acquire side

        // index dtype probe (after barrier; src is input, always valid)
        const long long* s64 = (const long long*)srcp;
        int ok = 1;
        #pragma unroll
        for (int i = 0; i < 8; ++i) {
            long long v = s64[i];
            if (v < 0 || v >= (long long)N_NODES) ok = 0;
        }
        s_is64 = ok;
    }
    __syncthreads();
    const int is64 = s_is64;

    // ========================= Phase 2: scatter ============================
    // Octet layout: 8 lanes x uint4 cover one 128B P-half row. Each thread
    // handles 2 edges: 4 idx loads + 4 uint4 gathers + 4 float4 stores.
    {
        const int oct = lane >> 3;     // 0..3 (edge slot within warp group)
        const int q   = lane & 7;      // 0..7 (16B column group)

        for (int chunk = blockIdx.x; chunk < CHUNKS; chunk += NB) {
            int ebase = chunk * 64 + wid * 8;
            int e0 = ebase + oct;
            int e1 = ebase + 4 + oct;
            int ec0 = e0 < N_EDGES ? e0 : (N_EDGES - 1);
            int ec1 = e1 < N_EDGES ? e1 : (N_EDGES - 1);

            int s0, d0, s1, d1;
            if (is64) {
                s0 = (int)__ldg(&((const long long*)srcp)[ec0]);
                d0 = (int)__ldg(&((const long long*)dstp)[ec0]);
                s1 = (int)__ldg(&((const long long*)srcp)[ec1]);
                d1 = (int)__ldg(&((const long long*)dstp)[ec1]);
            } else {
                s0 = __ldg(&((const int*)srcp)[ec0]);
                d0 = __ldg(&((const int*)dstp)[ec0]);
                s1 = __ldg(&((const int*)srcp)[ec1]);
                d1 = __ldg(&((const int*)dstp)[ec1]);
            }

            uint4 pu0 = *(const uint4*)&g_P[(unsigned)s0 * PDIM + q * 8];
            uint4 pv0 = *(const uint4*)&g_P[(unsigned)d0 * PDIM + OUT_CLASSES + q * 8];
            uint4 pu1 = *(const uint4*)&g_P[(unsigned)s1 * PDIM + q * 8];
            uint4 pv1 = *(const uint4*)&g_P[(unsigned)d1 * PDIM + OUT_CLASSES + q * 8];

            const __half2* u0 = (const __half2*)&pu0;
            const __half2* v0 = (const __half2*)&pv0;
            const __half2* u1 = (const __half2*)&pu1;
            const __half2* v1 = (const __half2*)&pv1;

            float4 r0a, r0b, r1a, r1b;
            {
                float2 a0 = __half22float2(u0[0]), c0 = __half22float2(v0[0]);
                float2 a1 = __half22float2(u0[1]), c1 = __half22float2(v0[1]);
                float2 a2 = __half22float2(u0[2]), c2 = __half22float2(v0[2]);
                float2 a3 = __half22float2(u0[3]), c3 = __half22float2(v0[3]);
                r0a = make_float4(a0.x + c0.x, a0.y + c0.y, a1.x + c1.x, a1.y + c1.y);
                r0b = make_float4(a2.x + c2.x, a2.y + c2.y, a3.x + c3.x, a3.y + c3.y);
            }
            {
                float2 a0 = __half22float2(u1[0]), c0 = __half22float2(v1[0]);
                float2 a1 = __half22float2(u1[1]), c1 = __half22float2(v1[1]);
                float2 a2 = __half22float2(u1[2]), c2 = __half22float2(v1[2]);
                float2 a3 = __half22float2(u1[3]), c3 = __half22float2(v1[3]);
                r1a = make_float4(a0.x + c0.x, a0.y + c0.y, a1.x + c1.x, a1.y + c1.y);
                r1b = make_float4(a2.x + c2.x, a2.y + c2.y, a3.x + c3.x, a3.y + c3.y);
            }

            if (e0 < N_EDGES) {
                float* o = &out[(size_t)(unsigned)e0 * OUT_CLASSES + q * 8];
                __stcs((float4*)o, r0a);
                __stcs((float4*)(o + 4), r0b);
            }
            if (e1 < N_EDGES) {
                float* o = &out[(size_t)(unsigned)e1 * OUT_CLASSES + q * 8];
                __stcs((float4*)o, r1a);
                __stcs((float4*)(o + 4), r1b);
            }
        }
    }
}

// ---------------------------------------------------------------------------
// Launch. Inputs: h[50000*128] f32, src[500000], dst[500000],
// W[64*256] f32, b[64] f32. Output: f32[500000*64].
// ---------------------------------------------------------------------------
extern "C" void kernel_launch(void* const* d_in, const int* in_sizes, int n_in,
                              void* d_out, int out_size) {
    const float* h   = (const float*)d_in[0];
    const void*  src = d_in[1];
    const void*  dst = d_in[2];
    const float* W   = (const float*)d_in[3];
    const float* b   = (const float*)d_in[4];
    float* out = (float*)d_out;
    (void)in_sizes; (void)n_in; (void)out_size;

    cudaFuncSetAttribute(fused_kernel,
                         cudaFuncAttributeMaxDynamicSharedMemorySize, GEMM_SMEM);

    fused_kernel<<<NB, 256, GEMM_SMEM>>>(h, W, b, src, dst, out);
}

// round 15
// speedup vs baseline: 1.1238x; 1.1238x over previous
#include <cuda_runtime.h>
#include <cuda_fp16.h>
#include <stdint.h>

#define N_NODES     50000
#define N_EDGES     500000
#define D_FEAT      128
#define OUT_CLASSES 64
#define PDIM        128   // [0:64) = Pu (+bias folded), [64:128) = Pv

// Per-node projections in fp16; 12.8 MB, L2-resident.
__device__ __align__(16) __half g_P[N_NODES * PDIM];

// ---------------------------------------------------------------------------
// Single-pass fp16 mma (legacy mma.sync — tcgen05 unavailable at compute_103).
// Measured error: 3.595e-4 (fp16-A/B/P in quadrature) << 1e-3.
// ---------------------------------------------------------------------------
__device__ __forceinline__ void mma_f16(float d[4], const uint32_t a[4], const uint32_t b[2]) {
    asm volatile(
        "mma.sync.aligned.m16n8k16.row.col.f32.f16.f16.f32 "
        "{%0,%1,%2,%3}, {%4,%5,%6,%7}, {%8,%9}, {%0,%1,%2,%3};\n"
        : "+f"(d[0]), "+f"(d[1]), "+f"(d[2]), "+f"(d[3])
        : "r"(a[0]), "r"(a[1]), "r"(a[2]), "r"(a[3]), "r"(b[0]), "r"(b[1]));
}

// ---------------------------------------------------------------------------
// Kernel 1: node projection GEMM, single-pass fp16, fused coalesced staging.
//   P[n][j] = sum_k h[n][k] * Wn[j][k] (+ b[j] for j<64)
// Tile 128m x 128n x 128k, 512 threads (16 warps, 4x4 grid of 32x32 warp
// tiles). B staged once per 128 nodes (traffic halved vs GM=64).
// smem: A 128x68 + B 128x68 u32 pairs = 69.6KB -> 2 CTAs/SM.
// ---------------------------------------------------------------------------
#define GM   128
#define GTHREADS 512
#define ST   68   // uint32 per row (64 f16x2 pairs + 4 pad); 68 mod 32 = 4
#define GEMM_SMEM ((128 + 128) * ST * 4)   // 69,632 B

__global__ __launch_bounds__(GTHREADS, 2)
void node_gemm_f16(const float* __restrict__ h,
                   const float* __restrict__ W,
                   const float* __restrict__ b) {
    extern __shared__ uint32_t sh[];
    uint32_t* Ah = sh;                // [128][ST] f16x2 pairs, k-major
    uint32_t* Bs = sh + 128 * ST;     // [128][ST] f16x2 pairs, k-major

    const int tid = threadIdx.x;
    const int n0  = blockIdx.x * GM;

    // Stage A (h tile, 128 x 128 f32 -> f16x2), coalesced float4
    #pragma unroll
    for (int it = 0; it < 8; ++it) {
        int idx = tid + it * GTHREADS;     // 0..4095
        int r  = idx >> 5;                 // 0..127
        int c4 = idx & 31;                 // float4 index; k = c4*4
        int node = n0 + r;
        float4 v = make_float4(0.f, 0.f, 0.f, 0.f);
        if (node < N_NODES)
            v = __ldg((const float4*)&h[(size_t)node * D_FEAT + c4 * 4]);
        __half2 h0 = __floats2half2_rn(v.x, v.y);
        __half2 h1 = __floats2half2_rn(v.z, v.w);
        *(uint2*)&Ah[r * ST + c4 * 2] = make_uint2(*(uint32_t*)&h0, *(uint32_t*)&h1);
    }
    // Stage B (Wn, 128 x 128 f32 -> f16x2), coalesced float4 per row
    #pragma unroll
    for (int it = 0; it < 8; ++it) {
        int idx = tid + it * GTHREADS;     // 0..4095
        int j  = idx >> 5;                 // 0..127
        int c4 = idx & 31;
        const float* ws = (j < OUT_CLASSES)
            ? &W[(size_t)j * 256 + c4 * 4]
            : &W[(size_t)(j - OUT_CLASSES) * 256 + 128 + c4 * 4];
        float4 v = __ldg((const float4*)ws);
        __half2 h0 = __floats2half2_rn(v.x, v.y);
        __half2 h1 = __floats2half2_rn(v.z, v.w);
        *(uint2*)&Bs[j * ST + c4 * 2] = make_uint2(*(uint32_t*)&h0, *(uint32_t*)&h1);
    }
    __syncthreads();

    const int wid    = tid >> 5;
    const int lane   = tid & 31;
    const int warp_m = wid & 3;        // 4 warps over 128 m
    const int warp_n = wid >> 2;       // 4 warps over 128 n
    const int m_base = warp_m * 32;
    const int n_base = warp_n * 32;
    const int lr = lane >> 2;          // 0..7
    const int lc = lane & 3;           // 0..3

    float acc[2][4][4];
    #pragma unroll
    for (int a = 0; a < 2; ++a)
        #pragma unroll
        for (int bn = 0; bn < 4; ++bn)
            #pragma unroll
            for (int c = 0; c < 4; ++c) acc[a][bn][c] = 0.0f;

    #pragma unroll 2
    for (int kc = 0; kc < 8; ++kc) {
        const int p0 = kc * 8 + lc;

        // B fragments from smem: 8-row scatter, conflict-free at stride 68.
        uint32_t bb[4][2];
        #pragma unroll
        for (int bn = 0; bn < 4; ++bn) {
            int nb = (n_base + bn * 8 + lr) * ST + p0;
            bb[bn][0] = Bs[nb];
            bb[bn][1] = Bs[nb + 4];
        }
        uint32_t ah[2][4];
        #pragma unroll
        for (int am = 0; am < 2; ++am) {
            int base = (m_base + am * 16 + lr) * ST + p0;
            ah[am][0] = Ah[base];
            ah[am][1] = Ah[base + 8 * ST];
            ah[am][2] = Ah[base + 4];
            ah[am][3] = Ah[base + 8 * ST + 4];
        }
        #pragma unroll
        for (int am = 0; am < 2; ++am)
            #pragma unroll
            for (int bn = 0; bn < 4; ++bn)
                mma_f16(acc[am][bn], ah[am], bb[bn]);
    }

    // Epilogue: fp16 P, bias folded into Pu columns (warp_n<2 <=> j<64).
    #pragma unroll
    for (int am = 0; am < 2; ++am) {
        int row = m_base + am * 16 + lr;
        #pragma unroll
        for (int bn = 0; bn < 4; ++bn) {
            int j = n_base + bn * 8 + 2 * lc;
            float bx = 0.f, by = 0.f;
            if (warp_n < 2) {
                float2 bv = __ldg((const float2*)&b[j]);
                bx = bv.x; by = bv.y;
            }
            int node = n0 + row;
            if (node < N_NODES) {
                __half2 v0 = __floats2half2_rn(acc[am][bn][0] + bx,
                                               acc[am][bn][1] + by);
                *(__half2*)&g_P[(size_t)node * PDIM + j] = v0;
            }
            int node2 = n0 + row + 8;
            if (node2 < N_NODES) {
                __half2 v1 = __floats2half2_rn(acc[am][bn][2] + bx,
                                               acc[am][bn][3] + by);
                *(__half2*)&g_P[(size_t)node2 * PDIM + j] = v1;
            }
        }
    }
}

// ---------------------------------------------------------------------------
// Kernel 2: edge scatter, octet layout: 8 lanes x uint4 cover one 128B
// P-half row; each thread handles 2 edges -> per warp 8 edges with half the
// LSU instructions of the uint2 layout at the same wavefront count.
// Streaming float4 output stores; guarded tail.
// ---------------------------------------------------------------------------
__global__ __launch_bounds__(256)
void edge_scatter_kernel(const void* __restrict__ srcp,
                         const void* __restrict__ dstp,
                         float* __restrict__ out) {
    __shared__ int s_is64;
    if (threadIdx.x == 0) {
        const long long* s64 = (const long long*)srcp;
        int ok = 1;
        #pragma unroll
        for (int i = 0; i < 8; ++i) {
            long long v = s64[i];
            if (v < 0 || v >= (long long)N_NODES) ok = 0;
        }
        s_is64 = ok;
    }
    __syncthreads();
    const int is64 = s_is64;

    const int warp = threadIdx.x >> 5;
    const int lane = threadIdx.x & 31;
    const int oct  = lane >> 3;    // 0..3: edge slot within warp group
    const int q    = lane & 7;     // 0..7: 16B column group

    const int ebase = (blockIdx.x * 8 + warp) * 8;
    int e0 = ebase + oct;
    int e1 = ebase + 4 + oct;
    int ec0 = e0 < N_EDGES ? e0 : (N_EDGES - 1);
    int ec1 = e1 < N_EDGES ? e1 : (N_EDGES - 1);

    int s0, d0, s1, d1;
    if (is64) {
        s0 = (int)__ldg(&((const long long*)srcp)[ec0]);
        d0 = (int)__ldg(&((const long long*)dstp)[ec0]);
        s1 = (int)__ldg(&((const long long*)srcp)[ec1]);
        d1 = (int)__ldg(&((const long long*)dstp)[ec1]);
    } else {
        s0 = __ldg(&((const int*)srcp)[ec0]);
        d0 = __ldg(&((const int*)dstp)[ec0]);
        s1 = __ldg(&((const int*)srcp)[ec1]);
        d1 = __ldg(&((const int*)dstp)[ec1]);
    }

    uint4 pu0 = *(const uint4*)&g_P[(unsigned)s0 * PDIM + q * 8];
    uint4 pv0 = *(const uint4*)&g_P[(unsigned)d0 * PDIM + OUT_CLASSES + q * 8];
    uint4 pu1 = *(const uint4*)&g_P[(unsigned)s1 * PDIM + q * 8];
    uint4 pv1 = *(const uint4*)&g_P[(unsigned)d1 * PDIM + OUT_CLASSES + q * 8];

    const __half2* u0 = (const __half2*)&pu0;
    const __half2* v0 = (const __half2*)&pv0;
    const __half2* u1 = (const __half2*)&pu1;
    const __half2* v1 = (const __half2*)&pv1;

    float4 r0a, r0b, r1a, r1b;
    {
        float2 a0 = __half22float2(u0[0]), c0 = __half22float2(v0[0]);
        float2 a1 = __half22float2(u0[1]), c1 = __half22float2(v0[1]);
        float2 a2 = __half22float2(u0[2]), c2 = __half22float2(v0[2]);
        float2 a3 = __half22float2(u0[3]), c3 = __half22float2(v0[3]);
        r0a = make_float4(a0.x + c0.x, a0.y + c0.y, a1.x + c1.x, a1.y + c1.y);
        r0b = make_float4(a2.x + c2.x, a2.y + c2.y, a3.x + c3.x, a3.y + c3.y);
    }
    {
        float2 a0 = __half22float2(u1[0]), c0 = __half22float2(v1[0]);
        float2 a1 = __half22float2(u1[1]), c1 = __half22float2(v1[1]);
        float2 a2 = __half22float2(u1[2]), c2 = __half22float2(v1[2]);
        float2 a3 = __half22float2(u1[3]), c3 = __half22float2(v1[3]);
        r1a = make_float4(a0.x + c0.x, a0.y + c0.y, a1.x + c1.x, a1.y + c1.y);
        r1b = make_float4(a2.x + c2.x, a2.y + c2.y, a3.x + c3.x, a3.y + c3.y);
    }

    if (e0 < N_EDGES) {
        float* o = &out[(size_t)(unsigned)e0 * OUT_CLASSES + q * 8];
        __stcs((float4*)o, r0a);
        __stcs((float4*)(o + 4), r0b);
    }
    if (e1 < N_EDGES) {
        float* o = &out[(size_t)(unsigned)e1 * OUT_CLASSES + q * 8];
        __stcs((float4*)o, r1a);
        __stcs((float4*)(o + 4), r1b);
    }
}

// ---------------------------------------------------------------------------
// Launch. Inputs: h[50000*128] f32, src[500000], dst[500000],
// W[64*256] f32, b[64] f32. Output: f32[500000*64].
// ---------------------------------------------------------------------------
extern "C" void kernel_launch(void* const* d_in, const int* in_sizes, int n_in,
                              void* d_out, int out_size) {
    const float* h   = (const float*)d_in[0];
    const void*  src = d_in[1];
    const void*  dst = d_in[2];
    const float* W   = (const float*)d_in[3];
    const float* b   = (const float*)d_in[4];
    float* out = (float*)d_out;
    (void)in_sizes; (void)n_in; (void)out_size;

    cudaFuncSetAttribute(node_gemm_f16,
                         cudaFuncAttributeMaxDynamicSharedMemorySize, GEMM_SMEM);

    const int gemm_blocks = (N_NODES + GM - 1) / GM;   // 391
    node_gemm_f16<<<gemm_blocks, GTHREADS, GEMM_SMEM>>>(h, W, b);

    // 64 edges per block (8 warps x 8): ceil(500000/64) = 7813
    edge_scatter_kernel<<<(N_EDGES + 63) / 64, 256>>>(src, dst, out);
}

// round 16
// speedup vs baseline: 1.4764x; 1.3138x over previous
#include <cuda_runtime.h>
#include <cuda_fp16.h>
#include <stdint.h>

#define N_NODES     50000
#define N_EDGES     500000
#define D_FEAT      128
#define OUT_CLASSES 64
#define PDIM        128   // [0:64) = Pu (+bias folded), [64:128) = Pv

// Per-node projections in fp16; 12.8 MB, L2-resident.
__device__ __align__(16) __half g_P[N_NODES * PDIM];

// ---------------------------------------------------------------------------
// Single-pass fp16 mma (legacy mma.sync — tcgen05 unavailable at compute_103).
// Measured error: 3.595e-4 (fp16-A/B/P in quadrature) << 1e-3.
// ---------------------------------------------------------------------------
__device__ __forceinline__ void mma_f16(float d[4], const uint32_t a[4], const uint32_t b[2]) {
    asm volatile(
        "mma.sync.aligned.m16n8k16.row.col.f32.f16.f16.f32 "
        "{%0,%1,%2,%3}, {%4,%5,%6,%7}, {%8,%9}, {%0,%1,%2,%3};\n"
        : "+f"(d[0]), "+f"(d[1]), "+f"(d[2]), "+f"(d[3])
        : "r"(a[0]), "r"(a[1]), "r"(a[2]), "r"(a[3]), "r"(b[0]), "r"(b[1]));
}

// ---------------------------------------------------------------------------
// Kernel 1: node projection GEMM (r15, measured ~12.9us).
//   P[n][j] = sum_k h[n][k] * Wn[j][k] (+ b[j] for j<64)
// Tile 128m x 128n x 128k, 512 threads, 4x4 grid of 32x32 warp tiles.
// smem: A 128x68 + B 128x68 u32 pairs = 69.6KB -> 2 CTAs/SM.
// ---------------------------------------------------------------------------
#define GM   128
#define GTHREADS 512
#define ST   68   // uint32 per row (64 f16x2 pairs + 4 pad); 68 mod 32 = 4
#define GEMM_SMEM ((128 + 128) * ST * 4)   // 69,632 B

__global__ __launch_bounds__(GTHREADS, 2)
void node_gemm_f16(const float* __restrict__ h,
                   const float* __restrict__ W,
                   const float* __restrict__ b) {
    extern __shared__ uint32_t sh[];
    uint32_t* Ah = sh;                // [128][ST] f16x2 pairs, k-major
    uint32_t* Bs = sh + 128 * ST;     // [128][ST] f16x2 pairs, k-major

    const int tid = threadIdx.x;
    const int n0  = blockIdx.x * GM;

    // Stage A (h tile, 128 x 128 f32 -> f16x2), coalesced float4
    #pragma unroll
    for (int it = 0; it < 8; ++it) {
        int idx = tid + it * GTHREADS;     // 0..4095
        int r  = idx >> 5;                 // 0..127
        int c4 = idx & 31;                 // float4 index; k = c4*4
        int node = n0 + r;
        float4 v = make_float4(0.f, 0.f, 0.f, 0.f);
        if (node < N_NODES)
            v = __ldg((const float4*)&h[(size_t)node * D_FEAT + c4 * 4]);
        __half2 h0 = __floats2half2_rn(v.x, v.y);
        __half2 h1 = __floats2half2_rn(v.z, v.w);
        *(uint2*)&Ah[r * ST + c4 * 2] = make_uint2(*(uint32_t*)&h0, *(uint32_t*)&h1);
    }
    // Stage B (Wn, 128 x 128 f32 -> f16x2), coalesced float4 per row
    #pragma unroll
    for (int it = 0; it < 8; ++it) {
        int idx = tid + it * GTHREADS;     // 0..4095
        int j  = idx >> 5;                 // 0..127
        int c4 = idx & 31;
        const float* ws = (j < OUT_CLASSES)
            ? &W[(size_t)j * 256 + c4 * 4]
            : &W[(size_t)(j - OUT_CLASSES) * 256 + 128 + c4 * 4];
        float4 v = __ldg((const float4*)ws);
        __half2 h0 = __floats2half2_rn(v.x, v.y);
        __half2 h1 = __floats2half2_rn(v.z, v.w);
        *(uint2*)&Bs[j * ST + c4 * 2] = make_uint2(*(uint32_t*)&h0, *(uint32_t*)&h1);
    }
    __syncthreads();

    const int wid    = tid >> 5;
    const int lane   = tid & 31;
    const int warp_m = wid & 3;        // 4 warps over 128 m
    const int warp_n = wid >> 2;       // 4 warps over 128 n
    const int m_base = warp_m * 32;
    const int n_base = warp_n * 32;
    const int lr = lane >> 2;          // 0..7
    const int lc = lane & 3;           // 0..3

    float acc[2][4][4];
    #pragma unroll
    for (int a = 0; a < 2; ++a)
        #pragma unroll
        for (int bn = 0; bn < 4; ++bn)
            #pragma unroll
            for (int c = 0; c < 4; ++c) acc[a][bn][c] = 0.0f;

    #pragma unroll 2
    for (int kc = 0; kc < 8; ++kc) {
        const int p0 = kc * 8 + lc;

        uint32_t bb[4][2];
        #pragma unroll
        for (int bn = 0; bn < 4; ++bn) {
            int nb = (n_base + bn * 8 + lr) * ST + p0;
            bb[bn][0] = Bs[nb];
            bb[bn][1] = Bs[nb + 4];
        }
        uint32_t ah[2][4];
        #pragma unroll
        for (int am = 0; am < 2; ++am) {
            int base = (m_base + am * 16 + lr) * ST + p0;
            ah[am][0] = Ah[base];
            ah[am][1] = Ah[base + 8 * ST];
            ah[am][2] = Ah[base + 4];
            ah[am][3] = Ah[base + 8 * ST + 4];
        }
        #pragma unroll
        for (int am = 0; am < 2; ++am)
            #pragma unroll
            for (int bn = 0; bn < 4; ++bn)
                mma_f16(acc[am][bn], ah[am], bb[bn]);
    }

    // Epilogue: fp16 P, bias folded into Pu columns (warp_n<2 <=> j<64).
    #pragma unroll
    for (int am = 0; am < 2; ++am) {
        int row = m_base + am * 16 + lr;
        #pragma unroll
        for (int bn = 0; bn < 4; ++bn) {
            int j = n_base + bn * 8 + 2 * lc;
            float bx = 0.f, by = 0.f;
            if (warp_n < 2) {
                float2 bv = __ldg((const float2*)&b[j]);
                bx = bv.x; by = bv.y;
            }
            int node = n0 + row;
            if (node < N_NODES) {
                __half2 v0 = __floats2half2_rn(acc[am][bn][0] + bx,
                                               acc[am][bn][1] + by);
                *(__half2*)&g_P[(size_t)node * PDIM + j] = v0;
            }
            int node2 = n0 + row + 8;
            if (node2 < N_NODES) {
                __half2 v1 = __floats2half2_rn(acc[am][bn][2] + bx,
                                               acc[am][bn][3] + by);
                *(__half2*)&g_P[(size_t)node2 * PDIM + j] = v1;
            }
        }
    }
}

// ---------------------------------------------------------------------------
// Kernel 2: edge scatter — r12 version VERBATIM (best measured: 26.1us).
// uint2 gathers, 4 edges per half-warp, all loads front-batched (MLP 8),
// streaming float4 output stores; guarded tail.
// ---------------------------------------------------------------------------
__global__ __launch_bounds__(256)
void edge_scatter_kernel(const void* __restrict__ srcp,
                         const void* __restrict__ dstp,
                         float* __restrict__ out) {
    __shared__ int s_is64;
    if (threadIdx.x == 0) {
        const long long* s64 = (const long long*)srcp;
        int ok = 1;
        #pragma unroll
        for (int i = 0; i < 8; ++i) {
            long long v = s64[i];
            if (v < 0 || v >= (long long)N_NODES) ok = 0;
        }
        s_is64 = ok;
    }
    __syncthreads();
    const int is64 = s_is64;

    const int warp = threadIdx.x >> 5;
    const int lane = threadIdx.x & 31;
    const int half = lane >> 4;
    const int sub  = lane & 15;
    const long long ebase = ((long long)blockIdx.x * 8 + warp) * 8 + half * 4;

    long long e[4], s[4], d[4];
    #pragma unroll
    for (int i = 0; i < 4; ++i) {
        e[i] = ebase + i;
        long long ec = e[i] < N_EDGES ? e[i] : (long long)(N_EDGES - 1);
        if (is64) {
            s[i] = __ldg(&((const long long*)srcp)[ec]);
            d[i] = __ldg(&((const long long*)dstp)[ec]);
        } else {
            s[i] = __ldg(&((const int*)srcp)[ec]);
            d[i] = __ldg(&((const int*)dstp)[ec]);
        }
    }

    uint2 gu[4], gv[4];
    #pragma unroll
    for (int i = 0; i < 4; ++i) {
        gu[i] = *(const uint2*)&g_P[(size_t)s[i] * PDIM + sub * 4];
        gv[i] = *(const uint2*)&g_P[(size_t)d[i] * PDIM + OUT_CLASSES + sub * 4];
    }

    #pragma unroll
    for (int i = 0; i < 4; ++i) {
        float2 ux = __half22float2(*(__half2*)&gu[i].x);
        float2 uy = __half22float2(*(__half2*)&gu[i].y);
        float2 vx = __half22float2(*(__half2*)&gv[i].x);
        float2 vy = __half22float2(*(__half2*)&gv[i].y);
        float4 r = make_float4(ux.x + vx.x, ux.y + vx.y,
                               uy.x + vy.x, uy.y + vy.y);
        if (e[i] < N_EDGES)
            __stcs((float4*)&out[(size_t)e[i] * OUT_CLASSES + sub * 4], r);
    }
}

// ---------------------------------------------------------------------------
// Launch. Inputs: h[50000*128] f32, src[500000], dst[500000],
// W[64*256] f32, b[64] f32. Output: f32[500000*64].
// ---------------------------------------------------------------------------
extern "C" void kernel_launch(void* const* d_in, const int* in_sizes, int n_in,
                              void* d_out, int out_size) {
    const float* h   = (const float*)d_in[0];
    const void*  src = d_in[1];
    const void*  dst = d_in[2];
    const float* W   = (const float*)d_in[3];
    const float* b   = (const float*)d_in[4];
    float* out = (float*)d_out;
    (void)in_sizes; (void)n_in; (void)out_size;

    cudaFuncSetAttribute(node_gemm_f16,
                         cudaFuncAttributeMaxDynamicSharedMemorySize, GEMM_SMEM);

    const int gemm_blocks = (N_NODES + GM - 1) / GM;   // 391
    node_gemm_f16<<<gemm_blocks, GTHREADS, GEMM_SMEM>>>(h, W, b);

    // 64 edges per block (8 warps x 8): ceil(500000/64) = 7813
    edge_scatter_kernel<<<(N_EDGES + 63) / 64, 256>>>(src, dst, out);
}